// round 1
// baseline (speedup 1.0000x reference)
#include <cuda_runtime.h>
#include <math.h>

#define B_  2
#define T_  2048
#define C_  2048
#define H_  16
#define DH_ 128
#define L_  512
#define M_  (B_*T_)   // 4096 rows

// ---------------- scratch (device globals: allocation-free) ----------------
__device__ float g_kv_d[M_*L_];
__device__ float g_q_d [M_*L_];
__device__ float g_q   [M_*C_];   // (b,t,h,128) : [qc | rope(qr)]
__device__ float g_k   [M_*C_];   // (b,t,h,128) : [kc | rope(kr)]
__device__ float g_v   [M_*C_];   // (b,t,h,128)
__device__ float g_attn[M_*C_];

// ---------------- generic SGEMM: C[m,n] = sum_k A[m,k] * W[n,k] ----------------
// MODE 0: plain row-major output (ldc)
// MODE 1: concat-low  : col = (n/64)*128 + (n%64)           (k_c / q_c halves)
// MODE 2: rope + concat-high: col = (n/64)*128 + 64 + (n%64) (k_r / q_r halves)
#define BM 128
#define BN 64
#define BK 16

template<int MODE>
__global__ void __launch_bounds__(256) sgemm_k(const float* __restrict__ A,
                                               const float* __restrict__ W,
                                               float* __restrict__ Cout,
                                               int K, int ldc)
{
    __shared__ __align__(16) float As[BK][BM+4];
    __shared__ __align__(16) float Ws[BK][BN+4];

    const int tid = threadIdx.x;
    const int tx  = tid & 15;          // 16 col-threads
    const int ty  = tid >> 4;          // 16 row-threads
    const int m0  = blockIdx.y * BM;
    const int n0  = blockIdx.x * BN;

    // load assignments
    const int alr = tid >> 1;          // 0..127 A row in tile
    const int alk = (tid & 1) * 8;     // 0 or 8
    const int wlr = tid >> 2;          // 0..63 W row in tile
    const int wlk = (tid & 3) * 4;     // 0,4,8,12

    const float* Ap = A + (size_t)(m0 + alr) * K + alk;
    const float* Wp = W + (size_t)(n0 + wlr) * K + wlk;

    float acc[8][4] = {};

    for (int k0 = 0; k0 < K; k0 += BK) {
        float4 a0 = *(const float4*)(Ap + k0);
        float4 a1 = *(const float4*)(Ap + k0 + 4);
        float4 w0 = *(const float4*)(Wp + k0);
        As[alk+0][alr] = a0.x; As[alk+1][alr] = a0.y;
        As[alk+2][alr] = a0.z; As[alk+3][alr] = a0.w;
        As[alk+4][alr] = a1.x; As[alk+5][alr] = a1.y;
        As[alk+6][alr] = a1.z; As[alk+7][alr] = a1.w;
        Ws[wlk+0][wlr] = w0.x; Ws[wlk+1][wlr] = w0.y;
        Ws[wlk+2][wlr] = w0.z; Ws[wlk+3][wlr] = w0.w;
        __syncthreads();

        #pragma unroll
        for (int k = 0; k < BK; k++) {
            float a[8], b[4];
            *(float4*)&a[0] = *(const float4*)&As[k][ty*8];
            *(float4*)&a[4] = *(const float4*)&As[k][ty*8+4];
            *(float4*)&b[0] = *(const float4*)&Ws[k][tx*4];
            #pragma unroll
            for (int i = 0; i < 8; i++)
                #pragma unroll
                for (int j = 0; j < 4; j++)
                    acc[i][j] = fmaf(a[i], b[j], acc[i][j]);
        }
        __syncthreads();
    }

    #pragma unroll
    for (int i = 0; i < 8; i++) {
        const int m = m0 + ty*8 + i;
        const int n = n0 + tx*4;
        if (MODE == 0) {
            float4 v; v.x = acc[i][0]; v.y = acc[i][1]; v.z = acc[i][2]; v.w = acc[i][3];
            *(float4*)&Cout[(size_t)m * ldc + n] = v;
        } else if (MODE == 1) {
            const int col = ((n >> 6) << 7) + (n & 63);   // h*128 + d
            float4 v; v.x = acc[i][0]; v.y = acc[i][1]; v.z = acc[i][2]; v.w = acc[i][3];
            *(float4*)&Cout[(size_t)m * C_ + col] = v;
        } else {
            // interleaved RoPE over D=1024, then write to high half of head dim
            const int t = m & (T_ - 1);
            const int col = ((n >> 6) << 7) + 64 + (n & 63);
            float outv[4];
            #pragma unroll
            for (int j = 0; j < 4; j += 2) {
                const int p = (n + j) >> 1;            // pair index 0..511
                float freq = expf((float)(2 * p) * (-9.210340371976184f / 1024.0f));
                float ang = (float)t * freq;
                float sv, cv;
                sincosf(ang, &sv, &cv);
                outv[j]   = acc[i][j]   * cv - acc[i][j+1] * sv;
                outv[j+1] = acc[i][j+1] * cv + acc[i][j]   * sv;
            }
            *(float4*)&Cout[(size_t)m * C_ + col] = *(float4*)outv;
        }
    }
}

// ---------------- causal flash attention, fp32, d=128 ----------------
// grid (T/64, H, B), 256 threads. Tiles: 64 q-rows x 64 k-rows.
#define FS_QK 132   // row stride for 128-wide tiles (pad, keeps 16B alignment)
#define FS_P  68    // row stride for 64-wide P tile

__global__ void __launch_bounds__(256) flash_k(const float* __restrict__ Qg,
                                               const float* __restrict__ Kg,
                                               const float* __restrict__ Vg,
                                               float* __restrict__ Og)
{
    extern __shared__ __align__(16) float sm[];
    float* Qs = sm;                   // [64][FS_QK]
    float* Ks = Qs + 64 * FS_QK;      // [64][FS_QK]
    float* Vs = Ks + 64 * FS_QK;      // [64][FS_QK]
    float* Ps = Vs + 64 * FS_QK;      // [64][FS_P]

    const int tid = threadIdx.x;
    const int tx = tid & 15, ty = tid >> 4;
    const int qb = blockIdx.x, h = blockIdx.y, b = blockIdx.z;
    const int q0 = qb * 64;
    const size_t base = (size_t)b * T_ * C_ + (size_t)h * DH_;

    // load Q tile (64 x 128)
    #pragma unroll
    for (int i = 0; i < 8; i++) {
        int idx = i * 256 + tid;
        int r = idx >> 5, c4 = (idx & 31) << 2;
        *(float4*)(Qs + r * FS_QK + c4) =
            *(const float4*)(Qg + base + (size_t)(q0 + r) * C_ + c4);
    }

    float o[4][8] = {};
    float mrow[4] = {-1e30f, -1e30f, -1e30f, -1e30f};
    float lrow[4] = {};
    const float scale = 0.088388347648318447f;  // 1/sqrt(128)

    for (int kb = 0; kb <= qb; kb++) {
        __syncthreads();   // prior PV reads done before overwriting tiles
        const int k0 = kb * 64;
        #pragma unroll
        for (int i = 0; i < 8; i++) {
            int idx = i * 256 + tid;
            int r = idx >> 5, c4 = (idx & 31) << 2;
            *(float4*)(Ks + r * FS_QK + c4) =
                *(const float4*)(Kg + base + (size_t)(k0 + r) * C_ + c4);
            *(float4*)(Vs + r * FS_QK + c4) =
                *(const float4*)(Vg + base + (size_t)(k0 + r) * C_ + c4);
        }
        __syncthreads();

        // S = Q K^T  (each thread: 4 rows x 4 cols, vectorized over d)
        float s[4][4] = {};
        for (int d = 0; d < 128; d += 4) {
            float qv[4][4], kv[4][4];
            #pragma unroll
            for (int i = 0; i < 4; i++)
                *(float4*)qv[i] = *(const float4*)(Qs + (ty*4+i) * FS_QK + d);
            #pragma unroll
            for (int j = 0; j < 4; j++)
                *(float4*)kv[j] = *(const float4*)(Ks + (tx*4+j) * FS_QK + d);
            #pragma unroll
            for (int i = 0; i < 4; i++)
                #pragma unroll
                for (int j = 0; j < 4; j++)
                    s[i][j] += qv[i][0]*kv[j][0] + qv[i][1]*kv[j][1]
                             + qv[i][2]*kv[j][2] + qv[i][3]*kv[j][3];
        }

        // scale + causal mask (only diagonal block needs the mask)
        if (kb == qb) {
            #pragma unroll
            for (int i = 0; i < 4; i++) {
                const int qr = q0 + ty*4 + i;
                #pragma unroll
                for (int j = 0; j < 4; j++) {
                    const int kc = k0 + tx*4 + j;
                    s[i][j] = (kc <= qr) ? s[i][j] * scale : -1e30f;
                }
            }
        } else {
            #pragma unroll
            for (int i = 0; i < 4; i++)
                #pragma unroll
                for (int j = 0; j < 4; j++)
                    s[i][j] *= scale;
        }

        // online softmax; row stats reduced across the 16-lane tx group
        #pragma unroll
        for (int i = 0; i < 4; i++) {
            float mx = fmaxf(fmaxf(s[i][0], s[i][1]), fmaxf(s[i][2], s[i][3]));
            #pragma unroll
            for (int off = 1; off < 16; off <<= 1)
                mx = fmaxf(mx, __shfl_xor_sync(0xffffffffu, mx, off));
            float mnew = fmaxf(mrow[i], mx);
            float corr = __expf(mrow[i] - mnew);
            float ps = 0.f;
            #pragma unroll
            for (int j = 0; j < 4; j++) {
                float e = __expf(s[i][j] - mnew);
                Ps[(ty*4+i) * FS_P + tx*4 + j] = e;
                ps += e;
            }
            #pragma unroll
            for (int off = 1; off < 16; off <<= 1)
                ps += __shfl_xor_sync(0xffffffffu, ps, off);
            lrow[i] = lrow[i] * corr + ps;
            mrow[i] = mnew;
            #pragma unroll
            for (int d8 = 0; d8 < 8; d8++) o[i][d8] *= corr;
        }
        __syncthreads();   // Ps visible to the whole block

        // O += P V  (each thread: 4 rows x 8 dims)
        #pragma unroll 4
        for (int c = 0; c < 64; c++) {
            float4 v0 = *(const float4*)(Vs + c * FS_QK + tx*8);
            float4 v1 = *(const float4*)(Vs + c * FS_QK + tx*8 + 4);
            #pragma unroll
            for (int i = 0; i < 4; i++) {
                float p = Ps[(ty*4+i) * FS_P + c];
                o[i][0] = fmaf(p, v0.x, o[i][0]);
                o[i][1] = fmaf(p, v0.y, o[i][1]);
                o[i][2] = fmaf(p, v0.z, o[i][2]);
                o[i][3] = fmaf(p, v0.w, o[i][3]);
                o[i][4] = fmaf(p, v1.x, o[i][4]);
                o[i][5] = fmaf(p, v1.y, o[i][5]);
                o[i][6] = fmaf(p, v1.z, o[i][6]);
                o[i][7] = fmaf(p, v1.w, o[i][7]);
            }
        }
    }

    // normalize + write (b, q, h, d) row-major into g_attn
    #pragma unroll
    for (int i = 0; i < 4; i++) {
        const float inv = 1.0f / lrow[i];
        float ov[8];
        #pragma unroll
        for (int d8 = 0; d8 < 8; d8++) ov[d8] = o[i][d8] * inv;
        float4* dst = (float4*)(Og + base + (size_t)(q0 + ty*4 + i) * C_ + tx*8);
        dst[0] = *(float4*)&ov[0];
        dst[1] = *(float4*)&ov[4];
    }
}

// ---------------- launcher ----------------
extern "C" void kernel_launch(void* const* d_in, const int* in_sizes, int n_in,
                              void* d_out, int out_size)
{
    const float* x     = (const float*)d_in[0];
    const float* W_kvD = (const float*)d_in[1];
    const float* W_qD  = (const float*)d_in[2];
    const float* W_kU  = (const float*)d_in[3];
    const float* W_vU  = (const float*)d_in[4];
    const float* W_qU  = (const float*)d_in[5];
    const float* W_rk  = (const float*)d_in[6];
    const float* W_rq  = (const float*)d_in[7];
    const float* W_o   = (const float*)d_in[8];
    float* out = (float*)d_out;

    float *kv_d, *q_d, *q, *k, *v, *attn;
    cudaGetSymbolAddress((void**)&kv_d, g_kv_d);
    cudaGetSymbolAddress((void**)&q_d,  g_q_d);
    cudaGetSymbolAddress((void**)&q,    g_q);
    cudaGetSymbolAddress((void**)&k,    g_k);
    cudaGetSymbolAddress((void**)&v,    g_v);
    cudaGetSymbolAddress((void**)&attn, g_attn);

    const int smem_flash = (3 * 64 * FS_QK + 64 * FS_P) * (int)sizeof(float);
    cudaFuncSetAttribute(flash_k, cudaFuncAttributeMaxDynamicSharedMemorySize, smem_flash);

    dim3 blk(256);
    // kv_d = x @ W_kvD^T    (4096 x 2048) -> (4096 x 512)
    sgemm_k<0><<<dim3(L_/BN,  M_/BM), blk>>>(x,    W_kvD, kv_d, C_, L_);
    // q_d  = x @ W_qD^T
    sgemm_k<0><<<dim3(L_/BN,  M_/BM), blk>>>(x,    W_qD,  q_d,  C_, L_);
    // k_c  = kv_d @ W_kU^T  -> low half of k heads
    sgemm_k<1><<<dim3(1024/BN, M_/BM), blk>>>(kv_d, W_kU, k,    L_, 0);
    // q_c  = q_d @ W_qU^T   -> low half of q heads
    sgemm_k<1><<<dim3(1024/BN, M_/BM), blk>>>(q_d,  W_qU, q,    L_, 0);
    // v    = kv_d @ W_vU^T  (contiguous (b,t,h,128))
    sgemm_k<0><<<dim3(C_/BN,  M_/BM), blk>>>(kv_d, W_vU, v,    L_, C_);
    // k_r  = rope(x @ W_rk^T)  -> high half of k heads
    sgemm_k<2><<<dim3(1024/BN, M_/BM), blk>>>(x,    W_rk, k,    C_, 0);
    // q_r  = rope(q_d @ W_rq^T) -> high half of q heads
    sgemm_k<2><<<dim3(1024/BN, M_/BM), blk>>>(q_d,  W_rq, q,    L_, 0);
    // causal attention
    flash_k<<<dim3(T_/64, H_, B_), blk, smem_flash>>>(q, k, v, attn);
    // out = attn @ W_o^T
    sgemm_k<0><<<dim3(C_/BN,  M_/BM), blk>>>(attn, W_o,  out,  C_, C_);
}

// round 2
// speedup vs baseline: 1.4862x; 1.4862x over previous
#include <cuda_runtime.h>
#include <math.h>

#define B_  2
#define T_  2048
#define C_  2048
#define H_  16
#define DH_ 128
#define L_  512
#define M_  (B_*T_)   // 4096 rows

// ---------------- scratch (device globals: allocation-free) ----------------
__device__ float g_kv_d[M_*L_];
__device__ float g_q_d [M_*L_];
__device__ float g_q   [M_*C_];   // (b,t,h,128) : [qc | rope(qr)]
__device__ float g_k   [M_*C_];   // (b,t,h,128) : [kc | rope(kr)]
__device__ float g_v   [M_*C_];   // (b,t,h,128)
__device__ float g_attn[M_*C_];

__device__ __forceinline__ unsigned f2tf(float f) {
    unsigned r;
    asm("cvt.rna.tf32.f32 %0, %1;" : "=r"(r) : "f"(f));
    return r;
}

// ---------------- tf32 tensor-core GEMM: C[m,n] = sum_k A[m,k] * W[n,k] ------
// MODE 0: plain row-major output (ldc)
// MODE 1: concat-low  : col = (n/64)*128 + (n%64)            (k_c / q_c halves)
// MODE 2: rope + concat-high: col = (n/64)*128 + 64 + (n%64) (k_r / q_r halves)
#define BM 128
#define BN 128
#define BK 32
#define SST 36   // smem row stride (floats): conflict-free frag loads + 16B-aligned STS

template<int MODE>
__global__ void __launch_bounds__(256) tgemm_k(const float* __restrict__ A,
                                               const float* __restrict__ W,
                                               float* __restrict__ Cout,
                                               int K, int ldc)
{
    __shared__ __align__(16) unsigned As[BM][SST];
    __shared__ __align__(16) unsigned Ws[BN][SST];

    const int tid  = threadIdx.x;
    const int m0   = blockIdx.y * BM;
    const int n0   = blockIdx.x * BN;

    const int w    = tid >> 5;
    const int lane = tid & 31;
    const int wm   = (w & 1) * 64;     // warp m-offset within tile
    const int wn   = (w >> 1) * 32;    // warp n-offset within tile
    const int g    = lane >> 2;        // group id (row within frag)
    const int t    = lane & 3;         // thread-in-group (k index)

    // global-load assignment: 2 threads per row, 16 k-cols each
    const int lrow = tid >> 1;         // 0..127
    const int lk   = (tid & 1) * 16;   // 0 or 16
    const float* Ap = A + (size_t)(m0 + lrow) * K + lk;
    const float* Wp = W + (size_t)(n0 + lrow) * K + lk;

    float acc[4][4][4] = {};
    float4 pa[4], pw[4];

    // preload first K-slab
    #pragma unroll
    for (int j = 0; j < 4; j++) {
        pa[j] = *(const float4*)(Ap + 4*j);
        pw[j] = *(const float4*)(Wp + 4*j);
    }

    for (int k0 = 0; k0 < K; k0 += BK) {
        // stage registers -> smem (with RN tf32 conversion)
        #pragma unroll
        for (int j = 0; j < 4; j++) {
            uint4 ua, uw;
            ua.x = f2tf(pa[j].x); ua.y = f2tf(pa[j].y);
            ua.z = f2tf(pa[j].z); ua.w = f2tf(pa[j].w);
            uw.x = f2tf(pw[j].x); uw.y = f2tf(pw[j].y);
            uw.z = f2tf(pw[j].z); uw.w = f2tf(pw[j].w);
            *(uint4*)&As[lrow][lk + 4*j] = ua;
            *(uint4*)&Ws[lrow][lk + 4*j] = uw;
        }
        __syncthreads();

        // prefetch next slab (hidden under the mma work below)
        if (k0 + BK < K) {
            #pragma unroll
            for (int j = 0; j < 4; j++) {
                pa[j] = *(const float4*)(Ap + k0 + BK + 4*j);
                pw[j] = *(const float4*)(Wp + k0 + BK + 4*j);
            }
        }

        #pragma unroll
        for (int kk = 0; kk < BK; kk += 8) {
            unsigned a[4][4], b[4][2];
            #pragma unroll
            for (int mf = 0; mf < 4; mf++) {
                const int r = wm + mf*16 + g;
                a[mf][0] = As[r    ][kk + t];
                a[mf][1] = As[r + 8][kk + t];
                a[mf][2] = As[r    ][kk + t + 4];
                a[mf][3] = As[r + 8][kk + t + 4];
            }
            #pragma unroll
            for (int nf = 0; nf < 4; nf++) {
                const int c = wn + nf*8 + g;
                b[nf][0] = Ws[c][kk + t];
                b[nf][1] = Ws[c][kk + t + 4];
            }
            #pragma unroll
            for (int mf = 0; mf < 4; mf++)
                #pragma unroll
                for (int nf = 0; nf < 4; nf++)
                    asm volatile(
                        "mma.sync.aligned.m16n8k8.row.col.f32.tf32.tf32.f32 "
                        "{%0,%1,%2,%3}, {%4,%5,%6,%7}, {%8,%9}, {%0,%1,%2,%3};"
                        : "+f"(acc[mf][nf][0]), "+f"(acc[mf][nf][1]),
                          "+f"(acc[mf][nf][2]), "+f"(acc[mf][nf][3])
                        : "r"(a[mf][0]), "r"(a[mf][1]), "r"(a[mf][2]), "r"(a[mf][3]),
                          "r"(b[nf][0]), "r"(b[nf][1]));
        }
        __syncthreads();
    }

    // ---------------- epilogue ----------------
    #pragma unroll
    for (int mf = 0; mf < 4; mf++) {
        #pragma unroll
        for (int nf = 0; nf < 4; nf++) {
            const int m = m0 + wm + mf*16 + g;     // rows m and m+8
            const int n = n0 + wn + nf*8 + 2*t;    // cols n and n+1
            float c0 = acc[mf][nf][0], c1 = acc[mf][nf][1];
            float c2 = acc[mf][nf][2], c3 = acc[mf][nf][3];
            if (MODE == 0) {
                float2 v0 = {c0, c1}, v1 = {c2, c3};
                *(float2*)&Cout[(size_t)m       * ldc + n] = v0;
                *(float2*)&Cout[(size_t)(m + 8) * ldc + n] = v1;
            } else if (MODE == 1) {
                const int col = ((n >> 6) << 7) + (n & 63);
                float2 v0 = {c0, c1}, v1 = {c2, c3};
                *(float2*)&Cout[(size_t)m       * C_ + col] = v0;
                *(float2*)&Cout[(size_t)(m + 8) * C_ + col] = v1;
            } else {
                const int col = ((n >> 6) << 7) + 64 + (n & 63);
                const int p = n >> 1;   // rope pair index
                const float freq = expf((float)(2 * p) * (-9.210340371976184f / 1024.0f));
                {
                    const int tt = m & (T_ - 1);
                    float sv, cv; sincosf((float)tt * freq, &sv, &cv);
                    float2 v = {c0 * cv - c1 * sv, c1 * cv + c0 * sv};
                    *(float2*)&Cout[(size_t)m * C_ + col] = v;
                }
                {
                    const int tt = (m + 8) & (T_ - 1);
                    float sv, cv; sincosf((float)tt * freq, &sv, &cv);
                    float2 v = {c2 * cv - c3 * sv, c3 * cv + c2 * sv};
                    *(float2*)&Cout[(size_t)(m + 8) * C_ + col] = v;
                }
            }
        }
    }
}

// ---------------- causal flash attention, fp32, d=128 ----------------
// grid (T/64, H, B), 256 threads. Tiles: 64 q-rows x 64 k-rows.
#define FS_QK 132
#define FS_P  68

__global__ void __launch_bounds__(256) flash_k(const float* __restrict__ Qg,
                                               const float* __restrict__ Kg,
                                               const float* __restrict__ Vg,
                                               float* __restrict__ Og)
{
    extern __shared__ __align__(16) float sm[];
    float* Qs = sm;
    float* Ks = Qs + 64 * FS_QK;
    float* Vs = Ks + 64 * FS_QK;
    float* Ps = Vs + 64 * FS_QK;

    const int tid = threadIdx.x;
    const int tx = tid & 15, ty = tid >> 4;
    const int qb = blockIdx.x, h = blockIdx.y, b = blockIdx.z;
    const int q0 = qb * 64;
    const size_t base = (size_t)b * T_ * C_ + (size_t)h * DH_;

    #pragma unroll
    for (int i = 0; i < 8; i++) {
        int idx = i * 256 + tid;
        int r = idx >> 5, c4 = (idx & 31) << 2;
        *(float4*)(Qs + r * FS_QK + c4) =
            *(const float4*)(Qg + base + (size_t)(q0 + r) * C_ + c4);
    }

    float o[4][8] = {};
    float mrow[4] = {-1e30f, -1e30f, -1e30f, -1e30f};
    float lrow[4] = {};
    const float scale = 0.088388347648318447f;

    for (int kb = 0; kb <= qb; kb++) {
        __syncthreads();
        const int k0 = kb * 64;
        #pragma unroll
        for (int i = 0; i < 8; i++) {
            int idx = i * 256 + tid;
            int r = idx >> 5, c4 = (idx & 31) << 2;
            *(float4*)(Ks + r * FS_QK + c4) =
                *(const float4*)(Kg + base + (size_t)(k0 + r) * C_ + c4);
            *(float4*)(Vs + r * FS_QK + c4) =
                *(const float4*)(Vg + base + (size_t)(k0 + r) * C_ + c4);
        }
        __syncthreads();

        float s[4][4] = {};
        for (int d = 0; d < 128; d += 4) {
            float qv[4][4], kv[4][4];
            #pragma unroll
            for (int i = 0; i < 4; i++)
                *(float4*)qv[i] = *(const float4*)(Qs + (ty*4+i) * FS_QK + d);
            #pragma unroll
            for (int j = 0; j < 4; j++)
                *(float4*)kv[j] = *(const float4*)(Ks + (tx*4+j) * FS_QK + d);
            #pragma unroll
            for (int i = 0; i < 4; i++)
                #pragma unroll
                for (int j = 0; j < 4; j++)
                    s[i][j] += qv[i][0]*kv[j][0] + qv[i][1]*kv[j][1]
                             + qv[i][2]*kv[j][2] + qv[i][3]*kv[j][3];
        }

        if (kb == qb) {
            #pragma unroll
            for (int i = 0; i < 4; i++) {
                const int qr = q0 + ty*4 + i;
                #pragma unroll
                for (int j = 0; j < 4; j++) {
                    const int kc = k0 + tx*4 + j;
                    s[i][j] = (kc <= qr) ? s[i][j] * scale : -1e30f;
                }
            }
        } else {
            #pragma unroll
            for (int i = 0; i < 4; i++)
                #pragma unroll
                for (int j = 0; j < 4; j++)
                    s[i][j] *= scale;
        }

        #pragma unroll
        for (int i = 0; i < 4; i++) {
            float mx = fmaxf(fmaxf(s[i][0], s[i][1]), fmaxf(s[i][2], s[i][3]));
            #pragma unroll
            for (int off = 1; off < 16; off <<= 1)
                mx = fmaxf(mx, __shfl_xor_sync(0xffffffffu, mx, off));
            float mnew = fmaxf(mrow[i], mx);
            float corr = __expf(mrow[i] - mnew);
            float ps = 0.f;
            #pragma unroll
            for (int j = 0; j < 4; j++) {
                float e = __expf(s[i][j] - mnew);
                Ps[(ty*4+i) * FS_P + tx*4 + j] = e;
                ps += e;
            }
            #pragma unroll
            for (int off = 1; off < 16; off <<= 1)
                ps += __shfl_xor_sync(0xffffffffu, ps, off);
            lrow[i] = lrow[i] * corr + ps;
            mrow[i] = mnew;
            #pragma unroll
            for (int d8 = 0; d8 < 8; d8++) o[i][d8] *= corr;
        }
        __syncthreads();

        #pragma unroll 4
        for (int c = 0; c < 64; c++) {
            float4 v0 = *(const float4*)(Vs + c * FS_QK + tx*8);
            float4 v1 = *(const float4*)(Vs + c * FS_QK + tx*8 + 4);
            #pragma unroll
            for (int i = 0; i < 4; i++) {
                float p = Ps[(ty*4+i) * FS_P + c];
                o[i][0] = fmaf(p, v0.x, o[i][0]);
                o[i][1] = fmaf(p, v0.y, o[i][1]);
                o[i][2] = fmaf(p, v0.z, o[i][2]);
                o[i][3] = fmaf(p, v0.w, o[i][3]);
                o[i][4] = fmaf(p, v1.x, o[i][4]);
                o[i][5] = fmaf(p, v1.y, o[i][5]);
                o[i][6] = fmaf(p, v1.z, o[i][6]);
                o[i][7] = fmaf(p, v1.w, o[i][7]);
            }
        }
    }

    #pragma unroll
    for (int i = 0; i < 4; i++) {
        const float inv = 1.0f / lrow[i];
        float ov[8];
        #pragma unroll
        for (int d8 = 0; d8 < 8; d8++) ov[d8] = o[i][d8] * inv;
        float4* dst = (float4*)(Og + base + (size_t)(q0 + ty*4 + i) * C_ + tx*8);
        dst[0] = *(float4*)&ov[0];
        dst[1] = *(float4*)&ov[4];
    }
}

// ---------------- launcher ----------------
extern "C" void kernel_launch(void* const* d_in, const int* in_sizes, int n_in,
                              void* d_out, int out_size)
{
    const float* x     = (const float*)d_in[0];
    const float* W_kvD = (const float*)d_in[1];
    const float* W_qD  = (const float*)d_in[2];
    const float* W_kU  = (const float*)d_in[3];
    const float* W_vU  = (const float*)d_in[4];
    const float* W_qU  = (const float*)d_in[5];
    const float* W_rk  = (const float*)d_in[6];
    const float* W_rq  = (const float*)d_in[7];
    const float* W_o   = (const float*)d_in[8];
    float* out = (float*)d_out;

    float *kv_d, *q_d, *q, *k, *v, *attn;
    cudaGetSymbolAddress((void**)&kv_d, g_kv_d);
    cudaGetSymbolAddress((void**)&q_d,  g_q_d);
    cudaGetSymbolAddress((void**)&q,    g_q);
    cudaGetSymbolAddress((void**)&k,    g_k);
    cudaGetSymbolAddress((void**)&v,    g_v);
    cudaGetSymbolAddress((void**)&attn, g_attn);

    const int smem_flash = (3 * 64 * FS_QK + 64 * FS_P) * (int)sizeof(float);
    cudaFuncSetAttribute(flash_k, cudaFuncAttributeMaxDynamicSharedMemorySize, smem_flash);

    dim3 blk(256);
    // kv_d = x @ W_kvD^T    (4096 x 2048) -> (4096 x 512)
    tgemm_k<0><<<dim3(L_/BN,   M_/BM), blk>>>(x,    W_kvD, kv_d, C_, L_);
    // q_d  = x @ W_qD^T
    tgemm_k<0><<<dim3(L_/BN,   M_/BM), blk>>>(x,    W_qD,  q_d,  C_, L_);
    // k_c  = kv_d @ W_kU^T  -> low half of k heads
    tgemm_k<1><<<dim3(1024/BN, M_/BM), blk>>>(kv_d, W_kU,  k,    L_, 0);
    // q_c  = q_d @ W_qU^T   -> low half of q heads
    tgemm_k<1><<<dim3(1024/BN, M_/BM), blk>>>(q_d,  W_qU,  q,    L_, 0);
    // v    = kv_d @ W_vU^T  (contiguous (b,t,h,128))
    tgemm_k<0><<<dim3(C_/BN,   M_/BM), blk>>>(kv_d, W_vU,  v,    L_, C_);
    // k_r  = rope(x @ W_rk^T)  -> high half of k heads
    tgemm_k<2><<<dim3(1024/BN, M_/BM), blk>>>(x,    W_rk,  k,    C_, 0);
    // q_r  = rope(q_d @ W_rq^T) -> high half of q heads
    tgemm_k<2><<<dim3(1024/BN, M_/BM), blk>>>(q_d,  W_rq,  q,    L_, 0);
    // causal attention
    flash_k<<<dim3(T_/64, H_, B_), blk, smem_flash>>>(q, k, v, attn);
    // out = attn @ W_o^T
    tgemm_k<0><<<dim3(C_/BN,   M_/BM), blk>>>(attn, W_o,  out,  C_, C_);
}

// round 9
// speedup vs baseline: 2.3748x; 1.5979x over previous
#include <cuda_runtime.h>
#include <math.h>
#include <stdint.h>

#define B_  2
#define T_  2048
#define C_  2048
#define H_  16
#define DH_ 128
#define L_  512
#define M_  (B_*T_)   // 4096 rows

// ---------------- scratch (device globals: allocation-free) ----------------
__device__ float g_kv_d[M_*L_];
__device__ float g_q_d [M_*L_];
__device__ float g_q   [M_*C_];   // (b,t,h,128) : [qc | rope(qr)]
__device__ float g_k   [M_*C_];   // (b,t,h,128) : [kc | rope(kr)]
__device__ float g_v   [M_*C_];   // (b,t,h,128)
__device__ float g_attn[M_*C_];

__device__ __forceinline__ unsigned f2tf(float f){
    unsigned r; asm("cvt.rna.tf32.f32 %0, %1;" : "=r"(r) : "f"(f)); return r;
}
__device__ __forceinline__ void split_tf(float x, unsigned &hi, unsigned &lo){
    hi = f2tf(x);
    lo = f2tf(x - __uint_as_float(hi));
}

#define MMA_TF32(d, a0,a1,a2,a3, b0,b1) \
    asm volatile("mma.sync.aligned.m16n8k8.row.col.f32.tf32.tf32.f32 " \
      "{%0,%1,%2,%3},{%4,%5,%6,%7},{%8,%9},{%0,%1,%2,%3};" \
      : "+f"((d)[0]),"+f"((d)[1]),"+f"((d)[2]),"+f"((d)[3]) \
      : "r"(a0),"r"(a1),"r"(a2),"r"(a3),"r"(b0),"r"(b1))

#define CP16(dst, src) \
    asm volatile("cp.async.cg.shared.global [%0], [%1], 16;" :: "r"(dst), "l"(src))

// ============ GEMM: C[m,n] = sum_k A[m,k] * W[n,k]  (tf32 mma, cp.async) ======
// MODE 0: plain row-major (ldc) | 1: concat-low | 2: rope+concat-high
// SPLIT: 3xtf32 (hi/lo) for ~fp32 accuracy
#define BM 128
#define BN 128
#define BK 32
#define SST 36
#define WOFF (2*BM*SST)

template<int MODE, bool SPLIT>
__global__ void __launch_bounds__(256) tgemm_k(const float* __restrict__ A,
                                               const float* __restrict__ W,
                                               float* __restrict__ Cout,
                                               int K, int ldc)
{
    extern __shared__ float sgm[];   // [2][BM][SST] A raw f32, then [2][BN][SST] W
    const int tid = threadIdx.x, m0 = blockIdx.y*BM, n0 = blockIdx.x*BN;
    const int w = tid>>5, lane = tid&31;
    const int wm = (w&1)*64, wn = (w>>1)*32, g = lane>>2, t = lane&3;
    const int crow = tid>>3, ccol = (tid&7)*4;
    const unsigned sbase = (unsigned)__cvta_generic_to_shared(sgm);

    const int KT = K/BK;
    float acc[4][4][4] = {};

    // prologue: stage 0
    #pragma unroll
    for (int i = 0; i < 4; i++) {
        int r = crow + i*32;
        CP16(sbase + (unsigned)(((0*BM + r)*SST + ccol)*4),      A + (size_t)(m0+r)*K + ccol);
        CP16(sbase + (unsigned)((WOFF + (0*BN + r)*SST + ccol)*4), W + (size_t)(n0+r)*K + ccol);
    }
    asm volatile("cp.async.commit_group;");

    for (int kt = 0; kt < KT; kt++) {
        const int s = kt & 1;
        if (kt + 1 < KT) {
            const int s2 = s ^ 1;
            #pragma unroll
            for (int i = 0; i < 4; i++) {
                int r = crow + i*32;
                CP16(sbase + (unsigned)(((s2*BM + r)*SST + ccol)*4),
                     A + (size_t)(m0+r)*K + (kt+1)*BK + ccol);
                CP16(sbase + (unsigned)((WOFF + (s2*BN + r)*SST + ccol)*4),
                     W + (size_t)(n0+r)*K + (kt+1)*BK + ccol);
            }
            asm volatile("cp.async.commit_group;");
            asm volatile("cp.async.wait_group 1;");
        } else {
            asm volatile("cp.async.wait_group 0;");
        }
        __syncthreads();

        const float* As  = sgm + (size_t)s*BM*SST;
        const float* Wsm = sgm + WOFF + (size_t)s*BN*SST;
        #pragma unroll
        for (int kk = 0; kk < BK; kk += 8) {
            unsigned ahi[16], bhi[8], alo[16], blo[8];
            #pragma unroll
            for (int mf = 0; mf < 4; mf++) {
                const float* p  = As + (wm + mf*16 + g    )*SST + kk;
                const float* p8 = As + (wm + mf*16 + g + 8)*SST + kk;
                if (SPLIT) {
                    split_tf(p [t],   ahi[mf*4+0], alo[mf*4+0]);
                    split_tf(p8[t],   ahi[mf*4+1], alo[mf*4+1]);
                    split_tf(p [t+4], ahi[mf*4+2], alo[mf*4+2]);
                    split_tf(p8[t+4], ahi[mf*4+3], alo[mf*4+3]);
                } else {
                    ahi[mf*4+0] = f2tf(p [t]);   ahi[mf*4+1] = f2tf(p8[t]);
                    ahi[mf*4+2] = f2tf(p [t+4]); ahi[mf*4+3] = f2tf(p8[t+4]);
                }
            }
            #pragma unroll
            for (int nf = 0; nf < 4; nf++) {
                const float* p = Wsm + (wn + nf*8 + g)*SST + kk;
                if (SPLIT) {
                    split_tf(p[t],   bhi[nf*2+0], blo[nf*2+0]);
                    split_tf(p[t+4], bhi[nf*2+1], blo[nf*2+1]);
                } else {
                    bhi[nf*2+0] = f2tf(p[t]); bhi[nf*2+1] = f2tf(p[t+4]);
                }
            }
            #pragma unroll
            for (int mf = 0; mf < 4; mf++)
                #pragma unroll
                for (int nf = 0; nf < 4; nf++) {
                    MMA_TF32(acc[mf][nf], ahi[mf*4+0],ahi[mf*4+1],ahi[mf*4+2],ahi[mf*4+3],
                             bhi[nf*2+0], bhi[nf*2+1]);
                    if (SPLIT) {
                        MMA_TF32(acc[mf][nf], ahi[mf*4+0],ahi[mf*4+1],ahi[mf*4+2],ahi[mf*4+3],
                                 blo[nf*2+0], blo[nf*2+1]);
                        MMA_TF32(acc[mf][nf], alo[mf*4+0],alo[mf*4+1],alo[mf*4+2],alo[mf*4+3],
                                 bhi[nf*2+0], bhi[nf*2+1]);
                    }
                }
        }
        __syncthreads();
    }

    // ---------------- epilogue ----------------
    #pragma unroll
    for (int mf = 0; mf < 4; mf++) {
        #pragma unroll
        for (int nf = 0; nf < 4; nf++) {
            const int m = m0 + wm + mf*16 + g;     // rows m and m+8
            const int n = n0 + wn + nf*8 + 2*t;    // cols n and n+1
            float c0 = acc[mf][nf][0], c1 = acc[mf][nf][1];
            float c2 = acc[mf][nf][2], c3 = acc[mf][nf][3];
            if (MODE == 0) {
                float2 v0 = {c0, c1}, v1 = {c2, c3};
                *(float2*)&Cout[(size_t)m       * ldc + n] = v0;
                *(float2*)&Cout[(size_t)(m + 8) * ldc + n] = v1;
            } else if (MODE == 1) {
                const int col = ((n >> 6) << 7) + (n & 63);
                float2 v0 = {c0, c1}, v1 = {c2, c3};
                *(float2*)&Cout[(size_t)m       * C_ + col] = v0;
                *(float2*)&Cout[(size_t)(m + 8) * C_ + col] = v1;
            } else {
                const int col = ((n >> 6) << 7) + 64 + (n & 63);
                const int p = n >> 1;   // rope pair index
                const float freq = expf((float)(2 * p) * (-9.210340371976184f / 1024.0f));
                {
                    const int tt = m & (T_ - 1);
                    float sv, cv; sincosf((float)tt * freq, &sv, &cv);
                    float2 v = {c0 * cv - c1 * sv, c1 * cv + c0 * sv};
                    *(float2*)&Cout[(size_t)m * C_ + col] = v;
                }
                {
                    const int tt = (m + 8) & (T_ - 1);
                    float sv, cv; sincosf((float)tt * freq, &sv, &cv);
                    float2 v = {c2 * cv - c3 * sv, c3 * cv + c2 * sv};
                    *(float2*)&Cout[(size_t)(m + 8) * C_ + col] = v;
                }
            }
        }
    }
}

// ============ causal flash attention on tf32 tensor cores ============
// q-tile 128 (8 warps x 16 q-cols), key-tile 64, d=128.
// Computes S^T = K Q^T and O^T = V^T P so all operands load naturally.
#define FST 132

__global__ void __launch_bounds__(256) flash_k(const float* __restrict__ Qg,
                                               const float* __restrict__ Kg,
                                               const float* __restrict__ Vg,
                                               float* __restrict__ Og)
{
    extern __shared__ unsigned usm[];
    unsigned* Qs = usm;                 // [128][FST] tf32 (pre-scaled)
    unsigned* Ks = usm + 128*FST;       // [64][FST] tf32
    unsigned* Vs = Ks  + 64*FST;        // [64][FST] tf32
    unsigned* Ps = Vs  + 64*FST;        // [64 keys][FST] P^T tf32 (warp-private cols)

    const int tid = threadIdx.x, w = tid>>5, lane = tid&31;
    const int g = lane>>2, t = lane&3;
    const int wq = w*16;                           // warp's q-col base
    const int qb = blockIdx.x, h = blockIdx.y, b = blockIdx.z;
    const int q0 = qb*128;
    const size_t base = (size_t)b*T_*C_ + (size_t)h*DH_;
    const float scale = 0.088388347648318447f;     // 1/sqrt(128)

    // stage Q (scaled, tf32)
    for (int idx = tid; idx < 128*32; idx += 256) {
        int r = idx>>5, c4 = (idx&31)<<2;
        float4 v = *(const float4*)(Qg + base + (size_t)(q0+r)*C_ + c4);
        uint4 u; u.x = f2tf(v.x*scale); u.y = f2tf(v.y*scale);
                 u.z = f2tf(v.z*scale); u.w = f2tf(v.w*scale);
        *(uint4*)(Qs + r*FST + c4) = u;
    }

    float mst[2][2] = {{-1e30f,-1e30f},{-1e30f,-1e30f}};
    float lst[2][2] = {};
    float o[8][2][4] = {};

    const int nkb = 2*qb + 2;
    for (int kb = 0; kb < nkb; kb++) {
        const int k0 = kb*64;
        __syncthreads();                 // prior reads of Ks/Vs done
        for (int idx = tid; idx < 64*32; idx += 256) {
            int r = idx>>5, c4 = (idx&31)<<2;
            float4 kv = *(const float4*)(Kg + base + (size_t)(k0+r)*C_ + c4);
            float4 vv = *(const float4*)(Vg + base + (size_t)(k0+r)*C_ + c4);
            uint4 uk; uk.x=f2tf(kv.x); uk.y=f2tf(kv.y); uk.z=f2tf(kv.z); uk.w=f2tf(kv.w);
            uint4 uv; uv.x=f2tf(vv.x); uv.y=f2tf(vv.y); uv.z=f2tf(vv.z); uv.w=f2tf(vv.w);
            *(uint4*)(Ks + r*FST + c4) = uk;
            *(uint4*)(Vs + r*FST + c4) = uv;
        }
        __syncthreads();

        const bool active = (q0 + wq + 15 >= k0);   // any unmasked row for this warp?
        if (active) {
            // ---- S^T[key][q] = K Q^T : A = K (natural), B = Q (natural) ----
            float sacc[4][2][4] = {};
            #pragma unroll
            for (int ks = 0; ks < 16; ks++) {
                unsigned bq[2][2];
                #pragma unroll
                for (int nf = 0; nf < 2; nf++) {
                    bq[nf][0] = Qs[(wq + nf*8 + g)*FST + ks*8 + t];
                    bq[nf][1] = Qs[(wq + nf*8 + g)*FST + ks*8 + t + 4];
                }
                #pragma unroll
                for (int mf = 0; mf < 4; mf++) {
                    unsigned a0 = Ks[(mf*16 + g    )*FST + ks*8 + t];
                    unsigned a1 = Ks[(mf*16 + g + 8)*FST + ks*8 + t];
                    unsigned a2 = Ks[(mf*16 + g    )*FST + ks*8 + t + 4];
                    unsigned a3 = Ks[(mf*16 + g + 8)*FST + ks*8 + t + 4];
                    MMA_TF32(sacc[mf][0], a0,a1,a2,a3, bq[0][0], bq[0][1]);
                    MMA_TF32(sacc[mf][1], a0,a1,a2,a3, bq[1][0], bq[1][1]);
                }
            }
            // causal mask (last two tiles only)
            if (kb >= nkb - 2) {
                #pragma unroll
                for (int mf = 0; mf < 4; mf++) {
                    const int key0 = k0 + mf*16 + g, key8 = key0 + 8;
                    #pragma unroll
                    for (int nf = 0; nf < 2; nf++) {
                        const int qg0 = q0 + wq + nf*8 + 2*t, qg1 = qg0 + 1;
                        if (key0 > qg0) sacc[mf][nf][0] = -1e30f;
                        if (key0 > qg1) sacc[mf][nf][1] = -1e30f;
                        if (key8 > qg0) sacc[mf][nf][2] = -1e30f;
                        if (key8 > qg1) sacc[mf][nf][3] = -1e30f;
                    }
                }
            }
            // ---- online softmax over keys (m-dim): per-thread cols, g-lane reduce ----
            #pragma unroll
            for (int nf = 0; nf < 2; nf++) {
                float mx0 = -1e30f, mx1 = -1e30f;
                #pragma unroll
                for (int mf = 0; mf < 4; mf++) {
                    mx0 = fmaxf(mx0, fmaxf(sacc[mf][nf][0], sacc[mf][nf][2]));
                    mx1 = fmaxf(mx1, fmaxf(sacc[mf][nf][1], sacc[mf][nf][3]));
                }
                #pragma unroll
                for (int off = 4; off < 32; off <<= 1) {
                    mx0 = fmaxf(mx0, __shfl_xor_sync(0xffffffffu, mx0, off));
                    mx1 = fmaxf(mx1, __shfl_xor_sync(0xffffffffu, mx1, off));
                }
                const float mn0 = fmaxf(mst[nf][0], mx0), mn1 = fmaxf(mst[nf][1], mx1);
                const float cr0 = __expf(mst[nf][0] - mn0), cr1 = __expf(mst[nf][1] - mn1);
                float s0 = 0.f, s1 = 0.f;
                #pragma unroll
                for (int mf = 0; mf < 4; mf++) {
                    float e0 = __expf(sacc[mf][nf][0] - mn0);
                    float e1 = __expf(sacc[mf][nf][1] - mn1);
                    float e2 = __expf(sacc[mf][nf][2] - mn0);
                    float e3 = __expf(sacc[mf][nf][3] - mn1);
                    s0 += e0 + e2; s1 += e1 + e3;
                    uint2 u01 = {f2tf(e0), f2tf(e1)};
                    uint2 u23 = {f2tf(e2), f2tf(e3)};
                    *(uint2*)(Ps + (mf*16 + g    )*FST + wq + nf*8 + 2*t) = u01;
                    *(uint2*)(Ps + (mf*16 + g + 8)*FST + wq + nf*8 + 2*t) = u23;
                }
                #pragma unroll
                for (int off = 4; off < 32; off <<= 1) {
                    s0 += __shfl_xor_sync(0xffffffffu, s0, off);
                    s1 += __shfl_xor_sync(0xffffffffu, s1, off);
                }
                lst[nf][0] = lst[nf][0]*cr0 + s0;
                lst[nf][1] = lst[nf][1]*cr1 + s1;
                mst[nf][0] = mn0; mst[nf][1] = mn1;
                #pragma unroll
                for (int mfd = 0; mfd < 8; mfd++) {
                    o[mfd][nf][0] *= cr0; o[mfd][nf][1] *= cr1;
                    o[mfd][nf][2] *= cr0; o[mfd][nf][3] *= cr1;
                }
            }
            __syncwarp();   // P^T visible within warp

            // ---- O^T[d][q] += V^T P : A = V^T (transposed LDS), B = P^T ----
            #pragma unroll
            for (int ks = 0; ks < 8; ks++) {
                unsigned bp[2][2];
                #pragma unroll
                for (int nf = 0; nf < 2; nf++) {
                    bp[nf][0] = Ps[(ks*8 + t    )*FST + wq + nf*8 + g];
                    bp[nf][1] = Ps[(ks*8 + t + 4)*FST + wq + nf*8 + g];
                }
                #pragma unroll
                for (int mfd = 0; mfd < 8; mfd++) {
                    unsigned a0 = Vs[(ks*8 + t    )*FST + mfd*16 + g];
                    unsigned a1 = Vs[(ks*8 + t    )*FST + mfd*16 + g + 8];
                    unsigned a2 = Vs[(ks*8 + t + 4)*FST + mfd*16 + g];
                    unsigned a3 = Vs[(ks*8 + t + 4)*FST + mfd*16 + g + 8];
                    MMA_TF32(o[mfd][0], a0,a1,a2,a3, bp[0][0], bp[0][1]);
                    MMA_TF32(o[mfd][1], a0,a1,a2,a3, bp[1][0], bp[1][1]);
                }
            }
        }
    }

    // ---- normalize + write O (transposed scatter) ----
    #pragma unroll
    for (int nf = 0; nf < 2; nf++) {
        const float i0 = 1.0f / lst[nf][0], i1 = 1.0f / lst[nf][1];
        const int qg0 = q0 + wq + nf*8 + 2*t;
        #pragma unroll
        for (int mfd = 0; mfd < 8; mfd++) {
            const int d = mfd*16 + g;
            Og[base + (size_t)qg0    *C_ + d    ] = o[mfd][nf][0]*i0;
            Og[base + (size_t)(qg0+1)*C_ + d    ] = o[mfd][nf][1]*i1;
            Og[base + (size_t)qg0    *C_ + d + 8] = o[mfd][nf][2]*i0;
            Og[base + (size_t)(qg0+1)*C_ + d + 8] = o[mfd][nf][3]*i1;
        }
    }
}

// ---------------- launcher ----------------
extern "C" void kernel_launch(void* const* d_in, const int* in_sizes, int n_in,
                              void* d_out, int out_size)
{
    const float* x     = (const float*)d_in[0];
    const float* W_kvD = (const float*)d_in[1];
    const float* W_qD  = (const float*)d_in[2];
    const float* W_kU  = (const float*)d_in[3];
    const float* W_vU  = (const float*)d_in[4];
    const float* W_qU  = (const float*)d_in[5];
    const float* W_rk  = (const float*)d_in[6];
    const float* W_rq  = (const float*)d_in[7];
    const float* W_o   = (const float*)d_in[8];
    float* out = (float*)d_out;

    float *kv_d, *q_d, *q, *k, *v, *attn;
    cudaGetSymbolAddress((void**)&kv_d, g_kv_d);
    cudaGetSymbolAddress((void**)&q_d,  g_q_d);
    cudaGetSymbolAddress((void**)&q,    g_q);
    cudaGetSymbolAddress((void**)&k,    g_k);
    cudaGetSymbolAddress((void**)&v,    g_v);
    cudaGetSymbolAddress((void**)&attn, g_attn);

    const int smem_gemmB = (2*BM*SST + 2*BN*SST) * (int)sizeof(float);   // 73728
    const int smem_flash = (128*FST + 3*64*FST) * (int)sizeof(unsigned); // 168960

    cudaFuncSetAttribute(tgemm_k<0,true>,  cudaFuncAttributeMaxDynamicSharedMemorySize, smem_gemmB);
    cudaFuncSetAttribute(tgemm_k<1,true>,  cudaFuncAttributeMaxDynamicSharedMemorySize, smem_gemmB);
    cudaFuncSetAttribute(tgemm_k<2,true>,  cudaFuncAttributeMaxDynamicSharedMemorySize, smem_gemmB);
    cudaFuncSetAttribute(tgemm_k<0,false>, cudaFuncAttributeMaxDynamicSharedMemorySize, smem_gemmB);
    cudaFuncSetAttribute(flash_k, cudaFuncAttributeMaxDynamicSharedMemorySize, smem_flash);

    dim3 blk(256);
    // kv_d = x @ W_kvD^T
    tgemm_k<0,true ><<<dim3(L_/BN,   M_/BM), blk, smem_gemmB>>>(x,    W_kvD, kv_d, C_, L_);
    // q_d  = x @ W_qD^T
    tgemm_k<0,true ><<<dim3(L_/BN,   M_/BM), blk, smem_gemmB>>>(x,    W_qD,  q_d,  C_, L_);
    // k_c -> low half of k heads
    tgemm_k<1,true ><<<dim3(1024/BN, M_/BM), blk, smem_gemmB>>>(kv_d, W_kU,  k,    L_, 0);
    // q_c -> low half of q heads
    tgemm_k<1,true ><<<dim3(1024/BN, M_/BM), blk, smem_gemmB>>>(q_d,  W_qU,  q,    L_, 0);
    // v
    tgemm_k<0,true ><<<dim3(C_/BN,   M_/BM), blk, smem_gemmB>>>(kv_d, W_vU,  v,    L_, C_);
    // k_r = rope(x @ W_rk^T) -> high half of k heads
    tgemm_k<2,true ><<<dim3(1024/BN, M_/BM), blk, smem_gemmB>>>(x,    W_rk,  k,    C_, 0);
    // q_r = rope(q_d @ W_rq^T) -> high half of q heads
    tgemm_k<2,true ><<<dim3(1024/BN, M_/BM), blk, smem_gemmB>>>(q_d,  W_rq,  q,    L_, 0);
    // causal attention (tensor cores)
    flash_k<<<dim3(T_/128, H_, B_), blk, smem_flash>>>(q, k, v, attn);
    // out = attn @ W_o^T  (single-pass tf32)
    tgemm_k<0,false><<<dim3(C_/BN,   M_/BM), blk, smem_gemmB>>>(attn, W_o,  out,  C_, C_);
}

// round 10
// speedup vs baseline: 2.8606x; 1.2045x over previous
#include <cuda_runtime.h>
#include <cuda_bf16.h>
#include <math.h>
#include <stdint.h>

#define B_  2
#define T_  2048
#define C_  2048
#define H_  16
#define DH_ 128
#define L_  512
#define M_  (B_*T_)   // 4096 rows

// ---------------- scratch (device globals: allocation-free) ----------------
__device__ float g_kv_d[M_*L_];
__device__ float g_q_d [M_*L_];
__device__ float g_q   [M_*C_];   // (b,t,h,128) : [qc | rope(qr)]
__device__ float g_k   [M_*C_];   // (b,t,h,128) : [kc | rope(kr)]
__device__ float g_v   [M_*C_];   // (b,t,h,128)
__device__ float g_attn[M_*C_];

__device__ __forceinline__ unsigned f2tf(float f){
    unsigned r; asm("cvt.rna.tf32.f32 %0, %1;" : "=r"(r) : "f"(f)); return r;
}
// split f32 pair (even k, odd k) into packed bf16x2 hi + lo words
__device__ __forceinline__ void split_bf2(float e, float o, unsigned &hi, unsigned &lo){
    __nv_bfloat162 h = __floats2bfloat162_rn(e, o);     // .x = e (low bits = lower k)
    float er = e - __bfloat162float(h.x);
    float og = o - __bfloat162float(h.y);
    __nv_bfloat162 l = __floats2bfloat162_rn(er, og);
    hi = *reinterpret_cast<unsigned*>(&h);
    lo = *reinterpret_cast<unsigned*>(&l);
}

#define MMA_TF32(d, a0,a1,a2,a3, b0,b1) \
    asm volatile("mma.sync.aligned.m16n8k8.row.col.f32.tf32.tf32.f32 " \
      "{%0,%1,%2,%3},{%4,%5,%6,%7},{%8,%9},{%0,%1,%2,%3};" \
      : "+f"((d)[0]),"+f"((d)[1]),"+f"((d)[2]),"+f"((d)[3]) \
      : "r"(a0),"r"(a1),"r"(a2),"r"(a3),"r"(b0),"r"(b1))

#define MMA_BF16(d, a0,a1,a2,a3, b0,b1) \
    asm volatile("mma.sync.aligned.m16n8k16.row.col.f32.bf16.bf16.f32 " \
      "{%0,%1,%2,%3},{%4,%5,%6,%7},{%8,%9},{%0,%1,%2,%3};" \
      : "+f"((d)[0]),"+f"((d)[1]),"+f"((d)[2]),"+f"((d)[3]) \
      : "r"(a0),"r"(a1),"r"(a2),"r"(a3),"r"(b0),"r"(b1))

#define CP16(dst, src) \
    asm volatile("cp.async.cg.shared.global [%0], [%1], 16;" :: "r"(dst), "l"(src))

// ============ GEMM: C[m,n] = sum_k A[m,k] * W[n,k] ============================
// MODE 0: plain row-major (ldc) | 1: concat-low | 2: rope+concat-high
// SPLIT true : bf16 3-term split (m16n8k16), ~1.5e-5 accuracy, smem stride 40
// SPLIT false: single-pass tf32 (m16n8k8),  ~2.4e-4 accuracy, smem stride 36
#define BM 128
#define BN 128
#define BK 32

template<int MODE, bool SPLIT>
__global__ void __launch_bounds__(256,2) tgemm_k(const float* __restrict__ A,
                                                 const float* __restrict__ W,
                                                 float* __restrict__ Cout,
                                                 int K, int ldc)
{
    constexpr int SST  = SPLIT ? 40 : 36;
    constexpr int WOFF = 2*BM*SST;
    extern __shared__ float sgm[];   // [2][BM][SST] A f32, then [2][BN][SST] W f32
    const int tid = threadIdx.x, m0 = blockIdx.y*BM, n0 = blockIdx.x*BN;
    const int w = tid>>5, lane = tid&31;
    const int wm = (w&1)*64, wn = (w>>1)*32, g = lane>>2, t = lane&3;
    const int crow = tid>>3, ccol = (tid&7)*4;
    const unsigned sbase = (unsigned)__cvta_generic_to_shared(sgm);

    const int KT = K/BK;
    float acc[4][4][4] = {};

    // prologue: stage 0
    #pragma unroll
    for (int i = 0; i < 4; i++) {
        int r = crow + i*32;
        CP16(sbase + (unsigned)(((0*BM + r)*SST + ccol)*4),        A + (size_t)(m0+r)*K + ccol);
        CP16(sbase + (unsigned)((WOFF + (0*BN + r)*SST + ccol)*4), W + (size_t)(n0+r)*K + ccol);
    }
    asm volatile("cp.async.commit_group;");

    for (int kt = 0; kt < KT; kt++) {
        const int s = kt & 1;
        if (kt + 1 < KT) {
            const int s2 = s ^ 1;
            #pragma unroll
            for (int i = 0; i < 4; i++) {
                int r = crow + i*32;
                CP16(sbase + (unsigned)(((s2*BM + r)*SST + ccol)*4),
                     A + (size_t)(m0+r)*K + (kt+1)*BK + ccol);
                CP16(sbase + (unsigned)((WOFF + (s2*BN + r)*SST + ccol)*4),
                     W + (size_t)(n0+r)*K + (kt+1)*BK + ccol);
            }
            asm volatile("cp.async.commit_group;");
            asm volatile("cp.async.wait_group 1;");
        } else {
            asm volatile("cp.async.wait_group 0;");
        }
        __syncthreads();

        const float* As  = sgm + (size_t)s*BM*SST;
        const float* Wsm = sgm + WOFF + (size_t)s*BN*SST;

        if (SPLIT) {
            // ---- bf16 3-term split: 2 chunks of k=16 per BK=32 ----
            #pragma unroll
            for (int kk = 0; kk < BK; kk += 16) {
                unsigned ahi[16], alo[16], bhi[8], blo[8];
                #pragma unroll
                for (int mf = 0; mf < 4; mf++) {
                    const float* pr0 = As + (wm + mf*16 + g    )*SST + kk;
                    const float* pr8 = As + (wm + mf*16 + g + 8)*SST + kk;
                    float2 e00 = *(const float2*)(pr0 + 2*t);
                    float2 e10 = *(const float2*)(pr8 + 2*t);
                    float2 e01 = *(const float2*)(pr0 + 2*t + 8);
                    float2 e11 = *(const float2*)(pr8 + 2*t + 8);
                    split_bf2(e00.x, e00.y, ahi[mf*4+0], alo[mf*4+0]);
                    split_bf2(e10.x, e10.y, ahi[mf*4+1], alo[mf*4+1]);
                    split_bf2(e01.x, e01.y, ahi[mf*4+2], alo[mf*4+2]);
                    split_bf2(e11.x, e11.y, ahi[mf*4+3], alo[mf*4+3]);
                }
                #pragma unroll
                for (int nf = 0; nf < 4; nf++) {
                    const float* pc = Wsm + (wn + nf*8 + g)*SST + kk;
                    float2 f0 = *(const float2*)(pc + 2*t);
                    float2 f1 = *(const float2*)(pc + 2*t + 8);
                    split_bf2(f0.x, f0.y, bhi[nf*2+0], blo[nf*2+0]);
                    split_bf2(f1.x, f1.y, bhi[nf*2+1], blo[nf*2+1]);
                }
                #pragma unroll
                for (int mf = 0; mf < 4; mf++)
                    #pragma unroll
                    for (int nf = 0; nf < 4; nf++) {
                        MMA_BF16(acc[mf][nf], ahi[mf*4+0],ahi[mf*4+1],ahi[mf*4+2],ahi[mf*4+3],
                                 bhi[nf*2+0], bhi[nf*2+1]);
                        MMA_BF16(acc[mf][nf], ahi[mf*4+0],ahi[mf*4+1],ahi[mf*4+2],ahi[mf*4+3],
                                 blo[nf*2+0], blo[nf*2+1]);
                        MMA_BF16(acc[mf][nf], alo[mf*4+0],alo[mf*4+1],alo[mf*4+2],alo[mf*4+3],
                                 bhi[nf*2+0], bhi[nf*2+1]);
                    }
            }
        } else {
            // ---- single-pass tf32 (W_o) ----
            #pragma unroll
            for (int kk = 0; kk < BK; kk += 8) {
                unsigned a[16], b[8];
                #pragma unroll
                for (int mf = 0; mf < 4; mf++) {
                    const float* p  = As + (wm + mf*16 + g    )*SST + kk;
                    const float* p8 = As + (wm + mf*16 + g + 8)*SST + kk;
                    a[mf*4+0] = f2tf(p [t]);   a[mf*4+1] = f2tf(p8[t]);
                    a[mf*4+2] = f2tf(p [t+4]); a[mf*4+3] = f2tf(p8[t+4]);
                }
                #pragma unroll
                for (int nf = 0; nf < 4; nf++) {
                    const float* p = Wsm + (wn + nf*8 + g)*SST + kk;
                    b[nf*2+0] = f2tf(p[t]); b[nf*2+1] = f2tf(p[t+4]);
                }
                #pragma unroll
                for (int mf = 0; mf < 4; mf++)
                    #pragma unroll
                    for (int nf = 0; nf < 4; nf++)
                        MMA_TF32(acc[mf][nf], a[mf*4+0],a[mf*4+1],a[mf*4+2],a[mf*4+3],
                                 b[nf*2+0], b[nf*2+1]);
            }
        }
        __syncthreads();
    }

    // ---------------- epilogue ----------------
    #pragma unroll
    for (int mf = 0; mf < 4; mf++) {
        #pragma unroll
        for (int nf = 0; nf < 4; nf++) {
            const int m = m0 + wm + mf*16 + g;     // rows m and m+8
            const int n = n0 + wn + nf*8 + 2*t;    // cols n and n+1
            float c0 = acc[mf][nf][0], c1 = acc[mf][nf][1];
            float c2 = acc[mf][nf][2], c3 = acc[mf][nf][3];
            if (MODE == 0) {
                float2 v0 = {c0, c1}, v1 = {c2, c3};
                *(float2*)&Cout[(size_t)m       * ldc + n] = v0;
                *(float2*)&Cout[(size_t)(m + 8) * ldc + n] = v1;
            } else if (MODE == 1) {
                const int col = ((n >> 6) << 7) + (n & 63);
                float2 v0 = {c0, c1}, v1 = {c2, c3};
                *(float2*)&Cout[(size_t)m       * C_ + col] = v0;
                *(float2*)&Cout[(size_t)(m + 8) * C_ + col] = v1;
            } else {
                const int col = ((n >> 6) << 7) + 64 + (n & 63);
                const int p = n >> 1;   // rope pair index
                const float freq = expf((float)(2 * p) * (-9.210340371976184f / 1024.0f));
                {
                    const int tt = m & (T_ - 1);
                    float sv, cv; sincosf((float)tt * freq, &sv, &cv);
                    float2 v = {c0 * cv - c1 * sv, c1 * cv + c0 * sv};
                    *(float2*)&Cout[(size_t)m * C_ + col] = v;
                }
                {
                    const int tt = (m + 8) & (T_ - 1);
                    float sv, cv; sincosf((float)tt * freq, &sv, &cv);
                    float2 v = {c2 * cv - c3 * sv, c3 * cv + c2 * sv};
                    *(float2*)&Cout[(size_t)(m + 8) * C_ + col] = v;
                }
            }
        }
    }
}

// ============ causal flash attention on tf32 tensor cores ============
// q-tile 128 (8 warps x 16 q-cols), key-tile 64, d=128.
// Computes S^T = K Q^T and O^T = V^T P so all operands load naturally.
#define FST 132

__global__ void __launch_bounds__(256) flash_k(const float* __restrict__ Qg,
                                               const float* __restrict__ Kg,
                                               const float* __restrict__ Vg,
                                               float* __restrict__ Og)
{
    extern __shared__ unsigned usm[];
    unsigned* Qs = usm;                 // [128][FST] tf32 (pre-scaled)
    unsigned* Ks = usm + 128*FST;       // [64][FST] tf32
    unsigned* Vs = Ks  + 64*FST;        // [64][FST] tf32
    unsigned* Ps = Vs  + 64*FST;        // [64 keys][FST] P^T tf32 (warp-private cols)

    const int tid = threadIdx.x, w = tid>>5, lane = tid&31;
    const int g = lane>>2, t = lane&3;
    const int wq = w*16;                           // warp's q-col base
    const int qb = blockIdx.x, h = blockIdx.y, b = blockIdx.z;
    const int q0 = qb*128;
    const size_t base = (size_t)b*T_*C_ + (size_t)h*DH_;
    const float scale = 0.088388347648318447f;     // 1/sqrt(128)

    // stage Q (scaled, tf32)
    for (int idx = tid; idx < 128*32; idx += 256) {
        int r = idx>>5, c4 = (idx&31)<<2;
        float4 v = *(const float4*)(Qg + base + (size_t)(q0+r)*C_ + c4);
        uint4 u; u.x = f2tf(v.x*scale); u.y = f2tf(v.y*scale);
                 u.z = f2tf(v.z*scale); u.w = f2tf(v.w*scale);
        *(uint4*)(Qs + r*FST + c4) = u;
    }

    float mst[2][2] = {{-1e30f,-1e30f},{-1e30f,-1e30f}};
    float lst[2][2] = {};
    float o[8][2][4] = {};

    const int nkb = 2*qb + 2;
    for (int kb = 0; kb < nkb; kb++) {
        const int k0 = kb*64;
        __syncthreads();                 // prior reads of Ks/Vs done
        for (int idx = tid; idx < 64*32; idx += 256) {
            int r = idx>>5, c4 = (idx&31)<<2;
            float4 kv = *(const float4*)(Kg + base + (size_t)(k0+r)*C_ + c4);
            float4 vv = *(const float4*)(Vg + base + (size_t)(k0+r)*C_ + c4);
            uint4 uk; uk.x=f2tf(kv.x); uk.y=f2tf(kv.y); uk.z=f2tf(kv.z); uk.w=f2tf(kv.w);
            uint4 uv; uv.x=f2tf(vv.x); uv.y=f2tf(vv.y); uv.z=f2tf(vv.z); uv.w=f2tf(vv.w);
            *(uint4*)(Ks + r*FST + c4) = uk;
            *(uint4*)(Vs + r*FST + c4) = uv;
        }
        __syncthreads();

        const bool active = (q0 + wq + 15 >= k0);   // any unmasked row for this warp?
        if (active) {
            // ---- S^T[key][q] = K Q^T : A = K (natural), B = Q (natural) ----
            float sacc[4][2][4] = {};
            #pragma unroll
            for (int ks = 0; ks < 16; ks++) {
                unsigned bq[2][2];
                #pragma unroll
                for (int nf = 0; nf < 2; nf++) {
                    bq[nf][0] = Qs[(wq + nf*8 + g)*FST + ks*8 + t];
                    bq[nf][1] = Qs[(wq + nf*8 + g)*FST + ks*8 + t + 4];
                }
                #pragma unroll
                for (int mf = 0; mf < 4; mf++) {
                    unsigned a0 = Ks[(mf*16 + g    )*FST + ks*8 + t];
                    unsigned a1 = Ks[(mf*16 + g + 8)*FST + ks*8 + t];
                    unsigned a2 = Ks[(mf*16 + g    )*FST + ks*8 + t + 4];
                    unsigned a3 = Ks[(mf*16 + g + 8)*FST + ks*8 + t + 4];
                    MMA_TF32(sacc[mf][0], a0,a1,a2,a3, bq[0][0], bq[0][1]);
                    MMA_TF32(sacc[mf][1], a0,a1,a2,a3, bq[1][0], bq[1][1]);
                }
            }
            // causal mask (last two tiles only)
            if (kb >= nkb - 2) {
                #pragma unroll
                for (int mf = 0; mf < 4; mf++) {
                    const int key0 = k0 + mf*16 + g, key8 = key0 + 8;
                    #pragma unroll
                    for (int nf = 0; nf < 2; nf++) {
                        const int qg0 = q0 + wq + nf*8 + 2*t, qg1 = qg0 + 1;
                        if (key0 > qg0) sacc[mf][nf][0] = -1e30f;
                        if (key0 > qg1) sacc[mf][nf][1] = -1e30f;
                        if (key8 > qg0) sacc[mf][nf][2] = -1e30f;
                        if (key8 > qg1) sacc[mf][nf][3] = -1e30f;
                    }
                }
            }
            // ---- online softmax over keys (m-dim): per-thread cols, g-lane reduce ----
            #pragma unroll
            for (int nf = 0; nf < 2; nf++) {
                float mx0 = -1e30f, mx1 = -1e30f;
                #pragma unroll
                for (int mf = 0; mf < 4; mf++) {
                    mx0 = fmaxf(mx0, fmaxf(sacc[mf][nf][0], sacc[mf][nf][2]));
                    mx1 = fmaxf(mx1, fmaxf(sacc[mf][nf][1], sacc[mf][nf][3]));
                }
                #pragma unroll
                for (int off = 4; off < 32; off <<= 1) {
                    mx0 = fmaxf(mx0, __shfl_xor_sync(0xffffffffu, mx0, off));
                    mx1 = fmaxf(mx1, __shfl_xor_sync(0xffffffffu, mx1, off));
                }
                const float mn0 = fmaxf(mst[nf][0], mx0), mn1 = fmaxf(mst[nf][1], mx1);
                const float cr0 = __expf(mst[nf][0] - mn0), cr1 = __expf(mst[nf][1] - mn1);
                float s0 = 0.f, s1 = 0.f;
                #pragma unroll
                for (int mf = 0; mf < 4; mf++) {
                    float e0 = __expf(sacc[mf][nf][0] - mn0);
                    float e1 = __expf(sacc[mf][nf][1] - mn1);
                    float e2 = __expf(sacc[mf][nf][2] - mn0);
                    float e3 = __expf(sacc[mf][nf][3] - mn1);
                    s0 += e0 + e2; s1 += e1 + e3;
                    uint2 u01 = {f2tf(e0), f2tf(e1)};
                    uint2 u23 = {f2tf(e2), f2tf(e3)};
                    *(uint2*)(Ps + (mf*16 + g    )*FST + wq + nf*8 + 2*t) = u01;
                    *(uint2*)(Ps + (mf*16 + g + 8)*FST + wq + nf*8 + 2*t) = u23;
                }
                #pragma unroll
                for (int off = 4; off < 32; off <<= 1) {
                    s0 += __shfl_xor_sync(0xffffffffu, s0, off);
                    s1 += __shfl_xor_sync(0xffffffffu, s1, off);
                }
                lst[nf][0] = lst[nf][0]*cr0 + s0;
                lst[nf][1] = lst[nf][1]*cr1 + s1;
                mst[nf][0] = mn0; mst[nf][1] = mn1;
                #pragma unroll
                for (int mfd = 0; mfd < 8; mfd++) {
                    o[mfd][nf][0] *= cr0; o[mfd][nf][1] *= cr1;
                    o[mfd][nf][2] *= cr0; o[mfd][nf][3] *= cr1;
                }
            }
            __syncwarp();   // P^T visible within warp

            // ---- O^T[d][q] += V^T P : A = V^T (transposed LDS), B = P^T ----
            #pragma unroll
            for (int ks = 0; ks < 8; ks++) {
                unsigned bp[2][2];
                #pragma unroll
                for (int nf = 0; nf < 2; nf++) {
                    bp[nf][0] = Ps[(ks*8 + t    )*FST + wq + nf*8 + g];
                    bp[nf][1] = Ps[(ks*8 + t + 4)*FST + wq + nf*8 + g];
                }
                #pragma unroll
                for (int mfd = 0; mfd < 8; mfd++) {
                    unsigned a0 = Vs[(ks*8 + t    )*FST + mfd*16 + g];
                    unsigned a1 = Vs[(ks*8 + t    )*FST + mfd*16 + g + 8];
                    unsigned a2 = Vs[(ks*8 + t + 4)*FST + mfd*16 + g];
                    unsigned a3 = Vs[(ks*8 + t + 4)*FST + mfd*16 + g + 8];
                    MMA_TF32(o[mfd][0], a0,a1,a2,a3, bp[0][0], bp[0][1]);
                    MMA_TF32(o[mfd][1], a0,a1,a2,a3, bp[1][0], bp[1][1]);
                }
            }
        }
    }

    // ---- normalize + write O (transposed scatter) ----
    #pragma unroll
    for (int nf = 0; nf < 2; nf++) {
        const float i0 = 1.0f / lst[nf][0], i1 = 1.0f / lst[nf][1];
        const int qg0 = q0 + wq + nf*8 + 2*t;
        #pragma unroll
        for (int mfd = 0; mfd < 8; mfd++) {
            const int d = mfd*16 + g;
            Og[base + (size_t)qg0    *C_ + d    ] = o[mfd][nf][0]*i0;
            Og[base + (size_t)(qg0+1)*C_ + d    ] = o[mfd][nf][1]*i1;
            Og[base + (size_t)qg0    *C_ + d + 8] = o[mfd][nf][2]*i0;
            Og[base + (size_t)(qg0+1)*C_ + d + 8] = o[mfd][nf][3]*i1;
        }
    }
}

// ---------------- launcher ----------------
extern "C" void kernel_launch(void* const* d_in, const int* in_sizes, int n_in,
                              void* d_out, int out_size)
{
    const float* x     = (const float*)d_in[0];
    const float* W_kvD = (const float*)d_in[1];
    const float* W_qD  = (const float*)d_in[2];
    const float* W_kU  = (const float*)d_in[3];
    const float* W_vU  = (const float*)d_in[4];
    const float* W_qU  = (const float*)d_in[5];
    const float* W_rk  = (const float*)d_in[6];
    const float* W_rq  = (const float*)d_in[7];
    const float* W_o   = (const float*)d_in[8];
    float* out = (float*)d_out;

    float *kv_d, *q_d, *q, *k, *v, *attn;
    cudaGetSymbolAddress((void**)&kv_d, g_kv_d);
    cudaGetSymbolAddress((void**)&q_d,  g_q_d);
    cudaGetSymbolAddress((void**)&q,    g_q);
    cudaGetSymbolAddress((void**)&k,    g_k);
    cudaGetSymbolAddress((void**)&v,    g_v);
    cudaGetSymbolAddress((void**)&attn, g_attn);

    const int smem_split = 2*(BM+BN)*40*(int)sizeof(float);   // 81920 (stride 40)
    const int smem_tf32  = 2*(BM+BN)*36*(int)sizeof(float);   // 73728 (stride 36)
    const int smem_flash = (128*FST + 3*64*FST) * (int)sizeof(unsigned); // 168960

    cudaFuncSetAttribute(tgemm_k<0,true>,  cudaFuncAttributeMaxDynamicSharedMemorySize, smem_split);
    cudaFuncSetAttribute(tgemm_k<1,true>,  cudaFuncAttributeMaxDynamicSharedMemorySize, smem_split);
    cudaFuncSetAttribute(tgemm_k<2,true>,  cudaFuncAttributeMaxDynamicSharedMemorySize, smem_split);
    cudaFuncSetAttribute(tgemm_k<0,false>, cudaFuncAttributeMaxDynamicSharedMemorySize, smem_tf32);
    cudaFuncSetAttribute(flash_k, cudaFuncAttributeMaxDynamicSharedMemorySize, smem_flash);

    dim3 blk(256);
    // kv_d = x @ W_kvD^T
    tgemm_k<0,true ><<<dim3(L_/BN,   M_/BM), blk, smem_split>>>(x,    W_kvD, kv_d, C_, L_);
    // q_d  = x @ W_qD^T
    tgemm_k<0,true ><<<dim3(L_/BN,   M_/BM), blk, smem_split>>>(x,    W_qD,  q_d,  C_, L_);
    // k_c -> low half of k heads
    tgemm_k<1,true ><<<dim3(1024/BN, M_/BM), blk, smem_split>>>(kv_d, W_kU,  k,    L_, 0);
    // q_c -> low half of q heads
    tgemm_k<1,true ><<<dim3(1024/BN, M_/BM), blk, smem_split>>>(q_d,  W_qU,  q,    L_, 0);
    // v
    tgemm_k<0,true ><<<dim3(C_/BN,   M_/BM), blk, smem_split>>>(kv_d, W_vU,  v,    L_, C_);
    // k_r = rope(x @ W_rk^T) -> high half of k heads
    tgemm_k<2,true ><<<dim3(1024/BN, M_/BM), blk, smem_split>>>(x,    W_rk,  k,    C_, 0);
    // q_r = rope(q_d @ W_rq^T) -> high half of q heads
    tgemm_k<2,true ><<<dim3(1024/BN, M_/BM), blk, smem_split>>>(q_d,  W_rq,  q,    L_, 0);
    // causal attention (tensor cores)
    flash_k<<<dim3(T_/128, H_, B_), blk, smem_flash>>>(q, k, v, attn);
    // out = attn @ W_o^T  (single-pass tf32)
    tgemm_k<0,false><<<dim3(C_/BN,   M_/BM), blk, smem_tf32>>>(attn, W_o,  out,  C_, C_);
}